// round 5
// baseline (speedup 1.0000x reference)
#include <cuda_runtime.h>
#include <cuda_fp16.h>
#include <math.h>
#include <stdint.h>

#define I_DIM 32
#define J_DIM 32
#define S_DIM 256
#define H_DIM 768
#define NTH 256
#define CHUNKS_PER_TILE 12     // 768 / 64
#define NSTAGE 4
#define NTILES 2048            // 2 mtiles * 32 j * 32 i
#define GRIDX 152              // GB300 SM count

// smem byte offsets (from 128B-aligned base)
#define STAGE_STRIDE 49152     // Q 16K + K 32K
#define OFF_Q   0
#define OFF_K   16384
#define OFF_DTAB 196608
#define OFF_KM   197632
#define OFF_QM   198656
#define OFF_PM   199168
#define OFF_PSE  200192
#define OFF_PSC  201216
#define OFF_RED  202240
#define SMEM_DYN (202272 + 160)

// ----------------------------------------------------------- device scratch
__device__ __align__(16) __half g_qh[I_DIM * S_DIM * H_DIM];
__device__ __align__(16) __half g_kh[J_DIM * S_DIM * H_DIM];
__device__ float g_part[I_DIM * J_DIM * 2];

// --------------------------------------------------------------- asm helpers
__device__ __forceinline__ uint32_t smem_u32(const void* p) {
    uint32_t a;
    asm("{ .reg .u64 t; cvta.to.shared.u64 t, %1; cvt.u32.u64 %0, t; }" : "=r"(a) : "l"(p));
    return a;
}
__device__ __forceinline__ void cp16(uint32_t s, const void* g) {
    asm volatile("{ .reg .u64 gg; cvta.to.global.u64 gg, %1; cp.async.cg.shared.global [%0], [gg], 16; }"
                 :: "r"(s), "l"(g));
}
#define CP_COMMIT() asm volatile("cp.async.commit_group;" ::: "memory")
#define CP_WAIT(N)  asm volatile("cp.async.wait_group %0;" :: "n"(N) : "memory")

__device__ __forceinline__ void ldsm4(uint32_t* A, uint32_t addr) {
    asm volatile("ldmatrix.sync.aligned.m8n8.x4.shared.b16 {%0,%1,%2,%3}, [%4];"
                 : "=r"(A[0]), "=r"(A[1]), "=r"(A[2]), "=r"(A[3]) : "r"(addr));
}
__device__ __forceinline__ void lds32(uint32_t& v, uint32_t addr) {
    asm volatile("ld.shared.b32 %0, [%1];" : "=r"(v) : "r"(addr));
}
__device__ __forceinline__ void mma16816(float* c, const uint32_t* a, uint32_t b0, uint32_t b1) {
    asm volatile("mma.sync.aligned.m16n8k16.row.col.f32.f16.f16.f32 "
                 "{%0,%1,%2,%3}, {%4,%5,%6,%7}, {%8,%9}, {%0,%1,%2,%3};"
                 : "+f"(c[0]), "+f"(c[1]), "+f"(c[2]), "+f"(c[3])
                 : "r"(a[0]), "r"(a[1]), "r"(a[2]), "r"(a[3]), "r"(b0), "r"(b1));
}

// ------------------------------------------------- normalize -> fp16 (Q and K)
__global__ void norm_kernel(const float* __restrict__ q, const float* __restrict__ k) {
    const int row = blockIdx.x;
    const int local = (row < I_DIM * S_DIM) ? row : row - I_DIM * S_DIM;
    const float* x = ((row < I_DIM * S_DIM) ? q : k) + (size_t)local * H_DIM;
    __half* hi = ((row < I_DIM * S_DIM) ? g_qh : g_kh) + (size_t)local * H_DIM;

    float v0 = x[threadIdx.x], v1 = x[threadIdx.x + 256], v2 = x[threadIdx.x + 512];
    float s = v0 * v0 + v1 * v1 + v2 * v2;
    #pragma unroll
    for (int o = 16; o; o >>= 1) s += __shfl_xor_sync(0xffffffffu, s, o);

    __shared__ float red[8];
    __shared__ float inv;
    if ((threadIdx.x & 31) == 0) red[threadIdx.x >> 5] = s;
    __syncthreads();
    if (threadIdx.x == 0) {
        float t = 0.f;
        #pragma unroll
        for (int w = 0; w < 8; w++) t += red[w];
        inv = 1.0f / fmaxf(sqrtf(t), 1e-12f);
    }
    __syncthreads();
    const float iv = inv;
    hi[threadIdx.x]       = __float2half(v0 * iv);
    hi[threadIdx.x + 256] = __float2half(v1 * iv);
    hi[threadIdx.x + 512] = __float2half(v2 * iv);
}

// ----------------------------------------------------------- stage loader
// Tile rows have 64 halves (128B = 8 x 16B groups), swizzle: group ^= row&7.
__device__ __forceinline__ void load_stage(uint32_t qdst, uint32_t kdst,
                                           const char* qsrc, const char* ksrc, int tid) {
    #pragma unroll
    for (int it = 0; it < 4; it++) {               // Q: 128 rows
        const int idx = tid + it * NTH;
        const int row = idx >> 3, g = idx & 7, gs = g ^ (row & 7);
        cp16(qdst + row * 128 + gs * 16, qsrc + (size_t)row * 1536 + g * 16);
    }
    #pragma unroll
    for (int it = 0; it < 8; it++) {               // K: 256 rows
        const int idx = tid + it * NTH;
        const int row = idx >> 3, g = idx & 7, gs = g ^ (row & 7);
        cp16(kdst + row * 128 + gs * 16, ksrc + (size_t)row * 1536 + g * 16);
    }
}

// ----------------------------------------------------------- chunk compute
__device__ __forceinline__ void compute_chunk(
    uint32_t qs, uint32_t ks_, float acc[2][16][4],
    uint32_t arow_off0, uint32_t hb, uint32_t l7,
    uint32_t brow_off, uint32_t gid, uint32_t tig)
{
    #pragma unroll
    for (int ks = 0; ks < 4; ks++) {
        uint32_t A[2][4];
        #pragma unroll
        for (int mf = 0; mf < 2; mf++) {
            const uint32_t agrp = (2u * ks + hb) ^ l7;
            ldsm4(A[mf], qs + arow_off0 + mf * 2048 + (agrp << 4));
        }
        const uint32_t g0 = ((2u * ks) ^ gid) << 4;
        const uint32_t g1 = ((2u * ks + 1u) ^ gid) << 4;
        const uint32_t b0a = ks_ + brow_off + g0 + 4 * tig;
        const uint32_t b1a = ks_ + brow_off + g1 + 4 * tig;
        #pragma unroll
        for (int nf = 0; nf < 16; nf++) {
            uint32_t b0, b1;
            lds32(b0, b0a + nf * 1024); lds32(b1, b1a + nf * 1024);
            mma16816(acc[0][nf], A[0], b0, b1);
            mma16816(acc[1][nf], A[1], b0, b1);
        }
    }
}

// ------------------------------------- persistent fused pair GEMM + epilogue
__global__ __launch_bounds__(NTH, 1)
void pair_kernel(const float* __restrict__ q_mask, const float* __restrict__ k_mask,
                 const float* __restrict__ alpha_raw)
{
    extern __shared__ char smraw[];
    const uint32_t rawu = smem_u32(smraw);
    const uint32_t pad = (128u - (rawu & 127u)) & 127u;
    char* sb = smraw + pad;
    const uint32_t sbu = rawu + pad;

    const int bid = blockIdx.x;
    const int tid = threadIdx.x;
    const int wid = tid >> 5;
    const int lane = tid & 31;
    const int warp_m = wid & 3;
    const int warp_n = wid >> 2;
    const uint32_t gid = lane >> 2, tig = lane & 3;
    const uint32_t hb = lane >> 4, l7 = lane & 7;

    float* dtab = (float*)(sb + OFF_DTAB);
    float* km_s = (float*)(sb + OFF_KM);
    float* qm_s = (float*)(sb + OFF_QM);
    float* pm   = (float*)(sb + OFF_PM);
    float* pse  = (float*)(sb + OFF_PSE);
    float* psc  = (float*)(sb + OFF_PSC);
    float* redw = (float*)(sb + OFF_RED);

    const float araw  = __ldg(alpha_raw);
    const float alpha = fmaxf(araw, 0.0f) + log1pf(expf(-fabsf(araw)));
    dtab[tid] = expf(-alpha * (float)tid);   // first loop sync orders this

    const int ntiles = (NTILES - bid + GRIDX - 1) / GRIDX;
    const int total  = ntiles * CHUNKS_PER_TILE;

    const uint32_t arow_off0 = (warp_m * 32 + (lane & 15)) * 128;
    const uint32_t brow_off  = (warp_n * 128 + gid) * 128;

    // ---- load issuer for global chunk gl (decodes its own tile) ----
    auto issue_load = [&](int gl) {
        const int tl = gl / CHUNKS_PER_TILE;
        const int cl = gl - tl * CHUNKS_PER_TILE;
        const int t  = bid + GRIDX * tl;
        const int mt = t & 1, jj = (t >> 1) & 31, ii = t >> 6;
        const char* qsrc = (const char*)(g_qh + ((size_t)ii * S_DIM + mt * 128) * H_DIM) + cl * 128;
        const char* ksrc = (const char*)(g_kh + (size_t)jj * S_DIM * H_DIM) + cl * 128;
        const uint32_t st = sbu + (uint32_t)(gl & (NSTAGE - 1)) * STAGE_STRIDE;
        load_stage(st + OFF_Q, st + OFF_K, qsrc, ksrc, tid);
        CP_COMMIT();
    };

    // prologue: 3 chunks in flight
    issue_load(0); issue_load(1); issue_load(2);

    float acc[2][16][4];
    #pragma unroll
    for (int a = 0; a < 2; a++)
        #pragma unroll
        for (int b = 0; b < 16; b++)
            #pragma unroll
            for (int c = 0; c < 4; c++) acc[a][b][c] = 0.0f;

    for (int gc = 0; gc < total; gc++) {
        if (gc + 2 < total) CP_WAIT(2);
        else if (gc + 1 < total) CP_WAIT(1);
        else CP_WAIT(0);
        __syncthreads();   // data arrived AND all warps done reading stage (gc-1)%4

        // issue next load first (targets stage freed at gc-1), overlaps compute
        if (gc + 3 < total) issue_load(gc + 3);

        const uint32_t st = sbu + (uint32_t)(gc & (NSTAGE - 1)) * STAGE_STRIDE;
        compute_chunk(st + OFF_Q, st + OFF_K, acc,
                      arow_off0, hb, l7, brow_off, gid, tig);

        const int cl = gc % CHUNKS_PER_TILE;
        if (cl != CHUNKS_PER_TILE - 1) continue;

        // ---------------- epilogue for tile (gc / 12) ----------------
        const int t  = bid + GRIDX * (gc / CHUNKS_PER_TILE);
        const int mtile = t & 1, j = (t >> 1) & 31, i = t >> 6;

        km_s[tid] = k_mask[j * S_DIM + tid];
        if (tid < 128) qm_s[tid] = q_mask[i * S_DIM + mtile * 128 + tid];
        __syncthreads();

        #pragma unroll
        for (int mf = 0; mf < 2; mf++) {
            #pragma unroll
            for (int h = 0; h < 2; h++) {
                const int row_local = warp_m * 32 + mf * 16 + h * 8 + (int)gid;
                const int s_glob = mtile * 128 + row_local;
                const float qmr = qm_s[row_local];

                float lg[32];
                float mx = -3.0e38f;
                #pragma unroll
                for (int nf = 0; nf < 16; nf++) {
                    #pragma unroll
                    for (int dc = 0; dc < 2; dc++) {
                        const int tt = warp_n * 128 + nf * 8 + 2 * (int)tig + dc;
                        const float v = acc[mf][nf][h * 2 + dc];
                        const float valid = qmr * km_s[tt];
                        int d = s_glob - tt; d = d < 0 ? -d : d;
                        const float lv = v * dtab[d] * valid - (1.0f - valid) * 1e9f;
                        lg[nf * 2 + dc] = lv;
                        mx = fmaxf(mx, lv);
                    }
                }
                mx = fmaxf(mx, __shfl_xor_sync(0xffffffffu, mx, 1));
                mx = fmaxf(mx, __shfl_xor_sync(0xffffffffu, mx, 2));
                float se = 0.0f, sc = 0.0f;
                #pragma unroll
                for (int nf = 0; nf < 16; nf++) {
                    #pragma unroll
                    for (int dc = 0; dc < 2; dc++) {
                        const float e = __expf(lg[nf * 2 + dc] - mx);
                        se += e;
                        sc = fmaf(e, acc[mf][nf][h * 2 + dc], sc);
                    }
                }
                #pragma unroll
                for (int o = 1; o <= 2; o <<= 1) {
                    se += __shfl_xor_sync(0xffffffffu, se, o);
                    sc += __shfl_xor_sync(0xffffffffu, sc, o);
                }
                if (tig == 0) {
                    pm [warp_n * 128 + row_local] = mx;
                    pse[warp_n * 128 + row_local] = se;
                    psc[warp_n * 128 + row_local] = sc;
                }
            }
        }
        __syncthreads();

        float score = 0.0f;
        if (tid < 128) {
            const float m0 = pm[tid],        m1 = pm[128 + tid];
            const float nm = fmaxf(m0, m1);
            const float e0 = __expf(m0 - nm), e1 = __expf(m1 - nm);
            const float S  = pse[tid] * e0 + pse[128 + tid] * e1;
            const float C  = psc[tid] * e0 + psc[128 + tid] * e1;
            score = qm_s[tid] * (C / S);
        }
        #pragma unroll
        for (int o = 16; o; o >>= 1) score += __shfl_xor_sync(0xffffffffu, score, o);
        if (lane == 0) redw[wid] = score;
        __syncthreads();
        if (tid == 0) {
            float tot = 0.0f;
            #pragma unroll
            for (int w = 0; w < 8; w++) tot += redw[w];
            g_part[(i * J_DIM + j) * 2 + mtile] = tot;
        }

        // reset accumulators for next tile
        #pragma unroll
        for (int a = 0; a < 2; a++)
            #pragma unroll
            for (int b = 0; b < 16; b++)
                #pragma unroll
                for (int c = 0; c < 4; c++) acc[a][b][c] = 0.0f;
    }
}

// --------------------------------------------------------------- final reduce
__global__ void reduce_kernel(const float* __restrict__ q_mask, float* __restrict__ out) {
    __shared__ float dsh[8];
    const int tid = threadIdx.x;
    const int wid = tid >> 5, lane = tid & 31;
    const int i0 = blockIdx.x * 8;

    {
        const float* qm = q_mask + (i0 + wid) * S_DIM;
        float s = 0.0f;
        #pragma unroll
        for (int e = 0; e < 8; e++) s += qm[lane + e * 32];
        #pragma unroll
        for (int o = 16; o; o >>= 1) s += __shfl_xor_sync(0xffffffffu, s, o);
        if (lane == 0) dsh[wid] = fmaxf(s, 1.0f);
    }
    __syncthreads();

    const int idx = blockIdx.x * 256 + tid;
    const float dn = dsh[tid >> 5];
    out[idx] = (g_part[idx * 2] + g_part[idx * 2 + 1]) / dn;
}

// -------------------------------------------------------------------- launch
extern "C" void kernel_launch(void* const* d_in, const int* in_sizes, int n_in,
                              void* d_out, int out_size) {
    const float* q  = (const float*)d_in[0];
    const float* k  = (const float*)d_in[1];
    const float* qm = (const float*)d_in[2];
    const float* km = (const float*)d_in[3];
    const float* ar = (const float*)d_in[4];
    float* out = (float*)d_out;

    norm_kernel<<<(I_DIM + J_DIM) * S_DIM, 256>>>(q, k);

    static int smem_set = 0;
    if (!smem_set) {
        cudaFuncSetAttribute(pair_kernel, cudaFuncAttributeMaxDynamicSharedMemorySize, SMEM_DYN);
        smem_set = 1;
    }
    pair_kernel<<<GRIDX, NTH, SMEM_DYN>>>(qm, km, ar);

    reduce_kernel<<<4, 256>>>(qm, out);
}

// round 6
// speedup vs baseline: 1.0760x; 1.0760x over previous
#include <cuda_runtime.h>
#include <cuda_fp16.h>
#include <math.h>
#include <stdint.h>

#define I_DIM 32
#define J_DIM 32
#define S_DIM 256
#define H_DIM 768
#define NTH 256
#define NCHUNK 12          // 768 / 64
#define NSTAGE 4

// smem byte offsets (from 128B-aligned base)
#define STAGE_STRIDE 49152     // Q 16K + K 32K
#define OFF_Q   0
#define OFF_K   16384
#define OFF_DTAB 196608
#define OFF_KM   197632
#define OFF_QM   198656
#define OFF_PM   199168        // 4 * 128 floats
#define OFF_PSE  201216
#define OFF_PSC  203264
#define OFF_RED  205312
#define SMEM_DYN (205344 + 160)

// ----------------------------------------------------------- device scratch
__device__ __align__(16) __half g_qh[I_DIM * S_DIM * H_DIM];
__device__ __align__(16) __half g_kh[J_DIM * S_DIM * H_DIM];
__device__ float g_part[I_DIM * J_DIM * 2];

// --------------------------------------------------------------- asm helpers
__device__ __forceinline__ uint32_t smem_u32(const void* p) {
    uint32_t a;
    asm("{ .reg .u64 t; cvta.to.shared.u64 t, %1; cvt.u32.u64 %0, t; }" : "=r"(a) : "l"(p));
    return a;
}
__device__ __forceinline__ void cp16(uint32_t s, const void* g) {
    asm volatile("{ .reg .u64 gg; cvta.to.global.u64 gg, %1; cp.async.cg.shared.global [%0], [gg], 16; }"
                 :: "r"(s), "l"(g));
}
#define CP_COMMIT() asm volatile("cp.async.commit_group;" ::: "memory")
#define CP_WAIT(N)  asm volatile("cp.async.wait_group %0;" :: "n"(N) : "memory")

__device__ __forceinline__ void ldsm4(uint32_t* A, uint32_t addr) {
    asm volatile("ldmatrix.sync.aligned.m8n8.x4.shared.b16 {%0,%1,%2,%3}, [%4];"
                 : "=r"(A[0]), "=r"(A[1]), "=r"(A[2]), "=r"(A[3]) : "r"(addr));
}
__device__ __forceinline__ void ldsm2(uint32_t& b0, uint32_t& b1, uint32_t addr) {
    asm volatile("ldmatrix.sync.aligned.m8n8.x2.shared.b16 {%0,%1}, [%2];"
                 : "=r"(b0), "=r"(b1) : "r"(addr));
}
__device__ __forceinline__ void mma16816(float* c, const uint32_t* a, uint32_t b0, uint32_t b1) {
    asm volatile("mma.sync.aligned.m16n8k16.row.col.f32.f16.f16.f32 "
                 "{%0,%1,%2,%3}, {%4,%5,%6,%7}, {%8,%9}, {%0,%1,%2,%3};"
                 : "+f"(c[0]), "+f"(c[1]), "+f"(c[2]), "+f"(c[3])
                 : "r"(a[0]), "r"(a[1]), "r"(a[2]), "r"(a[3]), "r"(b0), "r"(b1));
}

// ------------------------------------------------- normalize -> fp16 (Q and K)
__global__ void norm_kernel(const float* __restrict__ q, const float* __restrict__ k) {
    const int row = blockIdx.x;
    const int local = (row < I_DIM * S_DIM) ? row : row - I_DIM * S_DIM;
    const float* x = ((row < I_DIM * S_DIM) ? q : k) + (size_t)local * H_DIM;
    __half* hi = ((row < I_DIM * S_DIM) ? g_qh : g_kh) + (size_t)local * H_DIM;

    float v0 = x[threadIdx.x], v1 = x[threadIdx.x + 256], v2 = x[threadIdx.x + 512];
    float s = v0 * v0 + v1 * v1 + v2 * v2;
    #pragma unroll
    for (int o = 16; o; o >>= 1) s += __shfl_xor_sync(0xffffffffu, s, o);

    __shared__ float red[8];
    __shared__ float inv;
    if ((threadIdx.x & 31) == 0) red[threadIdx.x >> 5] = s;
    __syncthreads();
    if (threadIdx.x == 0) {
        float t = 0.f;
        #pragma unroll
        for (int w = 0; w < 8; w++) t += red[w];
        inv = 1.0f / fmaxf(sqrtf(t), 1e-12f);
    }
    __syncthreads();
    const float iv = inv;
    hi[threadIdx.x]       = __float2half(v0 * iv);
    hi[threadIdx.x + 256] = __float2half(v1 * iv);
    hi[threadIdx.x + 512] = __float2half(v2 * iv);
}

// ----------------------------------------------------------- stage loader
// Tile rows have 64 halves (128B = 8 x 16B groups), swizzle: group ^= row&7.
__device__ __forceinline__ void load_stage(uint32_t qdst, uint32_t kdst,
                                           const char* qsrc, const char* ksrc, int tid) {
    #pragma unroll
    for (int it = 0; it < 4; it++) {               // Q: 128 rows
        const int idx = tid + it * NTH;
        const int row = idx >> 3, g = idx & 7, gs = g ^ (row & 7);
        cp16(qdst + row * 128 + gs * 16, qsrc + (size_t)row * 1536 + g * 16);
    }
    #pragma unroll
    for (int it = 0; it < 8; it++) {               // K: 256 rows
        const int idx = tid + it * NTH;
        const int row = idx >> 3, g = idx & 7, gs = g ^ (row & 7);
        cp16(kdst + row * 128 + gs * 16, ksrc + (size_t)row * 1536 + g * 16);
    }
}

// ----------------------------------------------------------- chunk compute
// Warp tiling: 2 m-warps (64 rows each) x 4 n-warps (64 cols each).
// acc[mf(4)][nf(8)][4]
__device__ __forceinline__ void compute_chunk(
    uint32_t qs, uint32_t ks_, float acc[4][8][4],
    uint32_t arow_off0, uint32_t hb, uint32_t l7,
    uint32_t brow_off, uint32_t msel, uint32_t bx)
{
    #pragma unroll
    for (int ks = 0; ks < 4; ks++) {
        uint32_t A[4][4];
        #pragma unroll
        for (int mf = 0; mf < 4; mf++) {
            const uint32_t agrp = (2u * ks + hb) ^ l7;
            ldsm4(A[mf], qs + arow_off0 + mf * 2048 + (agrp << 4));
        }
        const uint32_t bg = ((2u * ks + msel) ^ bx) << 4;
        #pragma unroll
        for (int nf = 0; nf < 8; nf++) {
            uint32_t b0, b1;
            ldsm2(b0, b1, ks_ + brow_off + nf * 1024 + bg);
            mma16816(acc[0][nf], A[0], b0, b1);
            mma16816(acc[1][nf], A[1], b0, b1);
            mma16816(acc[2][nf], A[2], b0, b1);
            mma16816(acc[3][nf], A[3], b0, b1);
        }
    }
}

// ------------------------------------------------ fused pair GEMM + epilogue
__global__ __launch_bounds__(NTH, 1)
void pair_kernel(const float* __restrict__ q_mask, const float* __restrict__ k_mask,
                 const float* __restrict__ alpha_raw)
{
    extern __shared__ char smraw[];
    const uint32_t rawu = smem_u32(smraw);
    const uint32_t pad = (128u - (rawu & 127u)) & 127u;
    char* sb = smraw + pad;
    const uint32_t sbu = rawu + pad;

    const int mtile = blockIdx.x;
    const int j = blockIdx.y;
    const int i = blockIdx.z;
    const int tid = threadIdx.x;
    const int wid = tid >> 5;
    const int lane = tid & 31;
    const int warp_m = wid & 1;        // 2 m-warps (64 s-rows each)
    const int warp_n = wid >> 1;       // 4 n-warps (64 t-cols each)
    const uint32_t gid = lane >> 2, tig = lane & 3;
    const uint32_t hb = lane >> 4, l7 = lane & 7;

    float* dtab = (float*)(sb + OFF_DTAB);
    float* km_s = (float*)(sb + OFF_KM);
    float* qm_s = (float*)(sb + OFF_QM);
    float* pm   = (float*)(sb + OFF_PM);
    float* pse  = (float*)(sb + OFF_PSE);
    float* psc  = (float*)(sb + OFF_PSC);
    float* redw = (float*)(sb + OFF_RED);

    const float araw  = __ldg(alpha_raw);
    const float alpha = fmaxf(araw, 0.0f) + log1pf(expf(-fabsf(araw)));
    dtab[tid] = expf(-alpha * (float)tid);
    km_s[tid] = k_mask[j * S_DIM + tid];
    if (tid < 128) qm_s[tid] = q_mask[i * S_DIM + mtile * 128 + tid];

    const char* qsrc = (const char*)(g_qh + ((size_t)i * S_DIM + mtile * 128) * H_DIM);
    const char* ksrc = (const char*)(g_kh + (size_t)j * S_DIM * H_DIM);

    // prologue: chunks 0..2 into stages 0..2
    #pragma unroll
    for (int c = 0; c < 3; c++) {
        load_stage(sbu + c * STAGE_STRIDE + OFF_Q, sbu + c * STAGE_STRIDE + OFF_K,
                   qsrc + c * 128, ksrc + c * 128, tid);
        CP_COMMIT();
    }

    float acc[4][8][4];
    #pragma unroll
    for (int a = 0; a < 4; a++)
        #pragma unroll
        for (int b = 0; b < 8; b++)
            #pragma unroll
            for (int c = 0; c < 4; c++) acc[a][b][c] = 0.0f;

    // A: rows warp_m*64 + mf*16 + (lane&15); swizzle row&7 == lane&7
    const uint32_t arow_off0 = (warp_m * 64 + (lane & 15)) * 128;
    // B (ldsm.x2): lanes 0-15 give rows n0+(lane&7); matrix sel = (lane>>3)&1
    const uint32_t brow_off = (warp_n * 64 + l7) * 128;
    const uint32_t msel = (lane >> 3) & 1;
    const uint32_t bx = l7;

    for (int c = 0; c < NCHUNK; c++) {
        if (c <= NCHUNK - 3) CP_WAIT(2);
        else if (c == NCHUNK - 2) CP_WAIT(1);
        else CP_WAIT(0);
        __syncthreads();   // chunk c data ready AND stage (c+3)%4 fully consumed

        if (c + 3 < NCHUNK) {   // issue into stage freed at iteration c-1
            const int cl = c + 3;
            const uint32_t st = sbu + (uint32_t)(cl & (NSTAGE - 1)) * STAGE_STRIDE;
            load_stage(st + OFF_Q, st + OFF_K, qsrc + cl * 128, ksrc + cl * 128, tid);
            CP_COMMIT();
        }

        const uint32_t st = sbu + (uint32_t)(c & (NSTAGE - 1)) * STAGE_STRIDE;
        compute_chunk(st + OFF_Q, st + OFF_K, acc,
                      arow_off0, hb, l7, brow_off, msel, bx);
    }

    // ---------------- epilogue: per-row softmax over t ----------------
    // Row owned by (warp_m, mf, h, gid); cols warp_n*64 + nf*8 + 2*tig + dc.
    #pragma unroll
    for (int mf = 0; mf < 4; mf++) {
        #pragma unroll
        for (int h = 0; h < 2; h++) {
            const int row_local = warp_m * 64 + mf * 16 + h * 8 + (int)gid;
            const int s_glob = mtile * 128 + row_local;
            const float qmr = qm_s[row_local];

            float lg[16];
            float mx = -3.0e38f;
            #pragma unroll
            for (int nf = 0; nf < 8; nf++) {
                #pragma unroll
                for (int dc = 0; dc < 2; dc++) {
                    const int t = warp_n * 64 + nf * 8 + 2 * (int)tig + dc;
                    const float v = acc[mf][nf][h * 2 + dc];
                    const float valid = qmr * km_s[t];
                    int d = s_glob - t; d = d < 0 ? -d : d;
                    const float lv = v * dtab[d] * valid - (1.0f - valid) * 1e9f;
                    lg[nf * 2 + dc] = lv;
                    mx = fmaxf(mx, lv);
                }
            }
            mx = fmaxf(mx, __shfl_xor_sync(0xffffffffu, mx, 1));
            mx = fmaxf(mx, __shfl_xor_sync(0xffffffffu, mx, 2));
            float se = 0.0f, sc = 0.0f;
            #pragma unroll
            for (int nf = 0; nf < 8; nf++) {
                #pragma unroll
                for (int dc = 0; dc < 2; dc++) {
                    const float e = __expf(lg[nf * 2 + dc] - mx);
                    se += e;
                    sc = fmaf(e, acc[mf][nf][h * 2 + dc], sc);
                }
            }
            #pragma unroll
            for (int o = 1; o <= 2; o <<= 1) {
                se += __shfl_xor_sync(0xffffffffu, se, o);
                sc += __shfl_xor_sync(0xffffffffu, sc, o);
            }
            if (tig == 0) {
                pm [warp_n * 128 + row_local] = mx;
                pse[warp_n * 128 + row_local] = se;
                psc[warp_n * 128 + row_local] = sc;
            }
        }
    }
    __syncthreads();

    float score = 0.0f;
    if (tid < 128) {
        float m = pm[tid], S = pse[tid], C = psc[tid];
        #pragma unroll
        for (int q = 1; q < 4; q++) {
            const float mq = pm[q * 128 + tid];
            const float nm = fmaxf(m, mq);
            const float e0 = __expf(m - nm), e1 = __expf(mq - nm);
            S = S * e0 + pse[q * 128 + tid] * e1;
            C = C * e0 + psc[q * 128 + tid] * e1;
            m = nm;
        }
        score = qm_s[tid] * (C / S);
    }
    #pragma unroll
    for (int o = 16; o; o >>= 1) score += __shfl_xor_sync(0xffffffffu, score, o);
    if (lane == 0) redw[wid] = score;
    __syncthreads();
    if (tid == 0) {
        float tot = 0.0f;
        #pragma unroll
        for (int w = 0; w < 8; w++) tot += redw[w];
        g_part[(i * J_DIM + j) * 2 + mtile] = tot;
    }
}

// --------------------------------------------------------------- final reduce
__global__ void reduce_kernel(const float* __restrict__ q_mask, float* __restrict__ out) {
    __shared__ float dsh[8];
    const int tid = threadIdx.x;
    const int wid = tid >> 5, lane = tid & 31;
    const int i0 = blockIdx.x * 8;

    {
        const float* qm = q_mask + (i0 + wid) * S_DIM;
        float s = 0.0f;
        #pragma unroll
        for (int e = 0; e < 8; e++) s += qm[lane + e * 32];
        #pragma unroll
        for (int o = 16; o; o >>= 1) s += __shfl_xor_sync(0xffffffffu, s, o);
        if (lane == 0) dsh[wid] = fmaxf(s, 1.0f);
    }
    __syncthreads();

    const int idx = blockIdx.x * 256 + tid;
    const float dn = dsh[tid >> 5];
    out[idx] = (g_part[idx * 2] + g_part[idx * 2 + 1]) / dn;
}

// -------------------------------------------------------------------- launch
extern "C" void kernel_launch(void* const* d_in, const int* in_sizes, int n_in,
                              void* d_out, int out_size) {
    const float* q  = (const float*)d_in[0];
    const float* k  = (const float*)d_in[1];
    const float* qm = (const float*)d_in[2];
    const float* km = (const float*)d_in[3];
    const float* ar = (const float*)d_in[4];
    float* out = (float*)d_out;

    norm_kernel<<<(I_DIM + J_DIM) * S_DIM, 256>>>(q, k);

    static int smem_set = 0;
    if (!smem_set) {
        cudaFuncSetAttribute(pair_kernel, cudaFuncAttributeMaxDynamicSharedMemorySize, SMEM_DYN);
        smem_set = 1;
    }
    dim3 grid(2, J_DIM, I_DIM);
    pair_kernel<<<grid, NTH, SMEM_DYN>>>(qm, km, ar);

    reduce_kernel<<<4, 256>>>(qm, out);
}

// round 7
// speedup vs baseline: 1.1797x; 1.0963x over previous
#include <cuda_runtime.h>
#include <cuda_fp16.h>
#include <math.h>
#include <stdint.h>

#define I_DIM 32
#define J_DIM 32
#define S_DIM 256
#define H_DIM 768
#define NTH 256
#define NCHUNK 12          // 768 / 64
#define NSTAGE 3

// smem byte offsets (from 128B-aligned base). Stage = Q 16K + K 16K.
#define STAGE_STRIDE 32768
#define OFF_Q   0
#define OFF_K   16384
#define OFF_DTAB 98304
#define OFF_KM   99328
#define OFF_QM   99840
#define OFF_PM   100352        // 4 n-warps * 128 rows
#define OFF_PSE  102400
#define OFF_PSC  104448
#define SMEM_DYN (106496 + 128)

// ----------------------------------------------------------- device scratch
__device__ __align__(16) __half g_qh[I_DIM * S_DIM * H_DIM];
__device__ __align__(16) __half g_kh[J_DIM * S_DIM * H_DIM];
// per-row softmax partials: [(i*32+j)*256 + s_glob]*2 + ntile
__device__ float g_pm [I_DIM * J_DIM * S_DIM * 2];
__device__ float g_pse[I_DIM * J_DIM * S_DIM * 2];
__device__ float g_psc[I_DIM * J_DIM * S_DIM * 2];

// --------------------------------------------------------------- asm helpers
__device__ __forceinline__ uint32_t smem_u32(const void* p) {
    uint32_t a;
    asm("{ .reg .u64 t; cvta.to.shared.u64 t, %1; cvt.u32.u64 %0, t; }" : "=r"(a) : "l"(p));
    return a;
}
__device__ __forceinline__ void cp16(uint32_t s, const void* g) {
    asm volatile("{ .reg .u64 gg; cvta.to.global.u64 gg, %1; cp.async.cg.shared.global [%0], [gg], 16; }"
                 :: "r"(s), "l"(g));
}
#define CP_COMMIT() asm volatile("cp.async.commit_group;" ::: "memory")
#define CP_WAIT(N)  asm volatile("cp.async.wait_group %0;" :: "n"(N) : "memory")

__device__ __forceinline__ void ldsm4(uint32_t* A, uint32_t addr) {
    asm volatile("ldmatrix.sync.aligned.m8n8.x4.shared.b16 {%0,%1,%2,%3}, [%4];"
                 : "=r"(A[0]), "=r"(A[1]), "=r"(A[2]), "=r"(A[3]) : "r"(addr));
}
__device__ __forceinline__ void ldsm2(uint32_t& b0, uint32_t& b1, uint32_t addr) {
    asm volatile("ldmatrix.sync.aligned.m8n8.x2.shared.b16 {%0,%1}, [%2];"
                 : "=r"(b0), "=r"(b1) : "r"(addr));
}
__device__ __forceinline__ void mma16816(float* c, const uint32_t* a, uint32_t b0, uint32_t b1) {
    asm volatile("mma.sync.aligned.m16n8k16.row.col.f32.f16.f16.f32 "
                 "{%0,%1,%2,%3}, {%4,%5,%6,%7}, {%8,%9}, {%0,%1,%2,%3};"
                 : "+f"(c[0]), "+f"(c[1]), "+f"(c[2]), "+f"(c[3])
                 : "r"(a[0]), "r"(a[1]), "r"(a[2]), "r"(a[3]), "r"(b0), "r"(b1));
}

// ------------------------------------------------- normalize -> fp16 (Q and K)
__global__ void norm_kernel(const float* __restrict__ q, const float* __restrict__ k) {
    const int row = blockIdx.x;
    const int local = (row < I_DIM * S_DIM) ? row : row - I_DIM * S_DIM;
    const float* x = ((row < I_DIM * S_DIM) ? q : k) + (size_t)local * H_DIM;
    __half* hi = ((row < I_DIM * S_DIM) ? g_qh : g_kh) + (size_t)local * H_DIM;

    float v0 = x[threadIdx.x], v1 = x[threadIdx.x + 256], v2 = x[threadIdx.x + 512];
    float s = v0 * v0 + v1 * v1 + v2 * v2;
    #pragma unroll
    for (int o = 16; o; o >>= 1) s += __shfl_xor_sync(0xffffffffu, s, o);

    __shared__ float red[8];
    __shared__ float inv;
    if ((threadIdx.x & 31) == 0) red[threadIdx.x >> 5] = s;
    __syncthreads();
    if (threadIdx.x == 0) {
        float t = 0.f;
        #pragma unroll
        for (int w = 0; w < 8; w++) t += red[w];
        inv = 1.0f / fmaxf(sqrtf(t), 1e-12f);
    }
    __syncthreads();
    const float iv = inv;
    hi[threadIdx.x]       = __float2half(v0 * iv);
    hi[threadIdx.x + 256] = __float2half(v1 * iv);
    hi[threadIdx.x + 512] = __float2half(v2 * iv);
}

// ----------------------------------------------------------- stage loader
// 128 rows x 64 halves (128B = 8 x 16B groups), swizzle: group ^= row&7.
__device__ __forceinline__ void load_stage(uint32_t qdst, uint32_t kdst,
                                           const char* qsrc, const char* ksrc, int tid) {
    #pragma unroll
    for (int it = 0; it < 4; it++) {               // Q: 128 rows
        const int idx = tid + it * NTH;
        const int row = idx >> 3, g = idx & 7, gs = g ^ (row & 7);
        cp16(qdst + row * 128 + gs * 16, qsrc + (size_t)row * 1536 + g * 16);
    }
    #pragma unroll
    for (int it = 0; it < 4; it++) {               // K: 128 rows
        const int idx = tid + it * NTH;
        const int row = idx >> 3, g = idx & 7, gs = g ^ (row & 7);
        cp16(kdst + row * 128 + gs * 16, ksrc + (size_t)row * 1536 + g * 16);
    }
}

// ----------------------------------------------------------- chunk compute
// Warp tiling: 2 m-warps (64 rows) x 4 n-warps (32 cols). acc[mf(4)][nf(4)][4]
__device__ __forceinline__ void compute_chunk(
    uint32_t qs, uint32_t ks_, float acc[4][4][4],
    uint32_t arow_off0, uint32_t hb, uint32_t l7,
    uint32_t brow_off, uint32_t msel, uint32_t bx)
{
    #pragma unroll
    for (int ks = 0; ks < 4; ks++) {
        uint32_t A[4][4];
        #pragma unroll
        for (int mf = 0; mf < 4; mf++) {
            const uint32_t agrp = (2u * ks + hb) ^ l7;
            ldsm4(A[mf], qs + arow_off0 + mf * 2048 + (agrp << 4));
        }
        const uint32_t bg = ((2u * ks + msel) ^ bx) << 4;
        #pragma unroll
        for (int nf = 0; nf < 4; nf++) {
            uint32_t b0, b1;
            ldsm2(b0, b1, ks_ + brow_off + nf * 1024 + bg);
            mma16816(acc[0][nf], A[0], b0, b1);
            mma16816(acc[1][nf], A[1], b0, b1);
            mma16816(acc[2][nf], A[2], b0, b1);
            mma16816(acc[3][nf], A[3], b0, b1);
        }
    }
}

// ------------------------------------------------ fused pair GEMM + partials
__global__ __launch_bounds__(NTH, 2)
void pair_kernel(const float* __restrict__ q_mask, const float* __restrict__ k_mask,
                 const float* __restrict__ alpha_raw)
{
    extern __shared__ char smraw[];
    const uint32_t rawu = smem_u32(smraw);
    const uint32_t pad = (128u - (rawu & 127u)) & 127u;
    char* sb = smraw + pad;
    const uint32_t sbu = rawu + pad;

    const int mtile = blockIdx.x & 1;
    const int ntile = blockIdx.x >> 1;
    const int j = blockIdx.y;
    const int i = blockIdx.z;
    const int tid = threadIdx.x;
    const int wid = tid >> 5;
    const int lane = tid & 31;
    const int warp_m = wid & 1;        // 2 m-warps (64 s-rows each)
    const int warp_n = wid >> 1;       // 4 n-warps (32 t-cols each)
    const uint32_t gid = lane >> 2, tig = lane & 3;
    const uint32_t hb = lane >> 4, l7 = lane & 7;

    float* dtab = (float*)(sb + OFF_DTAB);
    float* km_s = (float*)(sb + OFF_KM);
    float* qm_s = (float*)(sb + OFF_QM);
    float* pm   = (float*)(sb + OFF_PM);
    float* pse  = (float*)(sb + OFF_PSE);
    float* psc  = (float*)(sb + OFF_PSC);

    const float araw  = __ldg(alpha_raw);
    const float alpha = fmaxf(araw, 0.0f) + log1pf(expf(-fabsf(araw)));
    dtab[tid] = expf(-alpha * (float)tid);
    if (tid < 128) {
        km_s[tid] = k_mask[j * S_DIM + ntile * 128 + tid];
        qm_s[tid] = q_mask[i * S_DIM + mtile * 128 + tid];
    }

    const char* qsrc = (const char*)(g_qh + ((size_t)i * S_DIM + mtile * 128) * H_DIM);
    const char* ksrc = (const char*)(g_kh + ((size_t)j * S_DIM + ntile * 128) * H_DIM);

    // prologue: chunks 0,1 into stages 0,1
    #pragma unroll
    for (int c = 0; c < 2; c++) {
        load_stage(sbu + c * STAGE_STRIDE + OFF_Q, sbu + c * STAGE_STRIDE + OFF_K,
                   qsrc + c * 128, ksrc + c * 128, tid);
        CP_COMMIT();
    }

    float acc[4][4][4];
    #pragma unroll
    for (int a = 0; a < 4; a++)
        #pragma unroll
        for (int b = 0; b < 4; b++)
            #pragma unroll
            for (int c = 0; c < 4; c++) acc[a][b][c] = 0.0f;

    const uint32_t arow_off0 = (warp_m * 64 + (lane & 15)) * 128;
    const uint32_t brow_off  = (warp_n * 32 + l7) * 128;
    const uint32_t msel = (lane >> 3) & 1;
    const uint32_t bx = l7;

    for (int c = 0; c < NCHUNK; c++) {
        if (c + 1 < NCHUNK) CP_WAIT(1); else CP_WAIT(0);
        __syncthreads();   // chunk c data ready AND stage (c+2)%3 fully consumed

        if (c + 2 < NCHUNK) {
            const int cl = c + 2;
            const uint32_t st = sbu + (uint32_t)(cl % NSTAGE) * STAGE_STRIDE;
            load_stage(st + OFF_Q, st + OFF_K, qsrc + cl * 128, ksrc + cl * 128, tid);
            CP_COMMIT();
        }

        const uint32_t st = sbu + (uint32_t)(c % NSTAGE) * STAGE_STRIDE;
        compute_chunk(st + OFF_Q, st + OFF_K, acc,
                      arow_off0, hb, l7, brow_off, msel, bx);
    }

    // ------------ epilogue: per-row partial softmax over this t-half ------------
    #pragma unroll
    for (int mf = 0; mf < 4; mf++) {
        #pragma unroll
        for (int h = 0; h < 2; h++) {
            const int row_local = warp_m * 64 + mf * 16 + h * 8 + (int)gid;
            const int s_glob = mtile * 128 + row_local;
            const float qmr = qm_s[row_local];

            float lg[8];
            float mx = -3.0e38f;
            #pragma unroll
            for (int nf = 0; nf < 4; nf++) {
                #pragma unroll
                for (int dc = 0; dc < 2; dc++) {
                    const int tl = warp_n * 32 + nf * 8 + 2 * (int)tig + dc;
                    const int tg = ntile * 128 + tl;
                    const float v = acc[mf][nf][h * 2 + dc];
                    const float valid = qmr * km_s[tl];
                    int d = s_glob - tg; d = d < 0 ? -d : d;
                    const float lv = v * dtab[d] * valid - (1.0f - valid) * 1e9f;
                    lg[nf * 2 + dc] = lv;
                    mx = fmaxf(mx, lv);
                }
            }
            mx = fmaxf(mx, __shfl_xor_sync(0xffffffffu, mx, 1));
            mx = fmaxf(mx, __shfl_xor_sync(0xffffffffu, mx, 2));
            float se = 0.0f, sc = 0.0f;
            #pragma unroll
            for (int nf = 0; nf < 4; nf++) {
                #pragma unroll
                for (int dc = 0; dc < 2; dc++) {
                    const float e = __expf(lg[nf * 2 + dc] - mx);
                    se += e;
                    sc = fmaf(e, acc[mf][nf][h * 2 + dc], sc);
                }
            }
            #pragma unroll
            for (int o = 1; o <= 2; o <<= 1) {
                se += __shfl_xor_sync(0xffffffffu, se, o);
                sc += __shfl_xor_sync(0xffffffffu, sc, o);
            }
            if (tig == 0) {
                pm [warp_n * 128 + row_local] = mx;
                pse[warp_n * 128 + row_local] = se;
                psc[warp_n * 128 + row_local] = sc;
            }
        }
    }
    __syncthreads();

    if (tid < 128) {
        float m = pm[tid], S = pse[tid], C = psc[tid];
        #pragma unroll
        for (int q = 1; q < 4; q++) {
            const float mq = pm[q * 128 + tid];
            const float nm = fmaxf(m, mq);
            const float e0 = __expf(m - nm), e1 = __expf(mq - nm);
            S = S * e0 + pse[q * 128 + tid] * e1;
            C = C * e0 + psc[q * 128 + tid] * e1;
            m = nm;
        }
        const int gidx = (((i * J_DIM + j) * S_DIM) + mtile * 128 + tid) * 2 + ntile;
        g_pm [gidx] = m;
        g_pse[gidx] = S;
        g_psc[gidx] = C;
    }
}

// ------------------------------------- combine t-halves + masked mean over s
__global__ void combine_kernel(const float* __restrict__ q_mask, float* __restrict__ out) {
    __shared__ float rsc[8], rqm[8];
    const int ij = blockIdx.x;
    const int i = ij >> 5;
    const int s = threadIdx.x;
    const int lane = s & 31, wid = s >> 5;

    const int base = (ij * S_DIM + s) * 2;
    const float m0 = g_pm[base], m1 = g_pm[base + 1];
    const float nm = fmaxf(m0, m1);
    const float e0 = __expf(m0 - nm), e1 = __expf(m1 - nm);
    const float S = g_pse[base] * e0 + g_pse[base + 1] * e1;
    const float C = g_psc[base] * e0 + g_psc[base + 1] * e1;
    const float q = q_mask[i * S_DIM + s];
    float score = q * (C / S);
    float qv = q;
    #pragma unroll
    for (int o = 16; o; o >>= 1) {
        score += __shfl_xor_sync(0xffffffffu, score, o);
        qv    += __shfl_xor_sync(0xffffffffu, qv, o);
    }
    if (lane == 0) { rsc[wid] = score; rqm[wid] = qv; }
    __syncthreads();
    if (s == 0) {
        float ts = 0.f, tq = 0.f;
        #pragma unroll
        for (int w = 0; w < 8; w++) { ts += rsc[w]; tq += rqm[w]; }
        out[ij] = ts / fmaxf(tq, 1.0f);
    }
}

// Dummy: shifts launch-index alignment so ncu (-s 5) lands on pair_kernel.
__global__ void dummy_kernel() {}

// -------------------------------------------------------------------- launch
extern "C" void kernel_launch(void* const* d_in, const int* in_sizes, int n_in,
                              void* d_out, int out_size) {
    const float* q  = (const float*)d_in[0];
    const float* k  = (const float*)d_in[1];
    const float* qm = (const float*)d_in[2];
    const float* km = (const float*)d_in[3];
    const float* ar = (const float*)d_in[4];
    float* out = (float*)d_out;

    norm_kernel<<<(I_DIM + J_DIM) * S_DIM, 256>>>(q, k);

    static int smem_set = 0;
    if (!smem_set) {
        cudaFuncSetAttribute(pair_kernel, cudaFuncAttributeMaxDynamicSharedMemorySize, SMEM_DYN);
        smem_set = 1;
    }
    dim3 grid(4, J_DIM, I_DIM);
    pair_kernel<<<grid, NTH, SMEM_DYN>>>(qm, km, ar);

    combine_kernel<<<I_DIM * J_DIM, 256>>>(qm, out);
    dummy_kernel<<<1, 32>>>();
}